// round 8
// baseline (speedup 1.0000x reference)
#include <cuda_runtime.h>
#include <cstdint>

// PARCOR -> LPC (Levinson step-up), rows x 25 f32. HBM-bound.
// One-shot CTAs: one 51.2 KB bulk-async load per CTA, register recurrence,
// per-warp 3.2 KB bulk-async stores. L2 evict_first hints on both streams.
// 512 thr, 4 CTAs/SM -> 2048 thr/SM (full occupancy).

#define ORDER 25
#define RPB   512                       // rows per tile, one thread per row
#define TILE_FLOATS (RPB * ORDER)       // 12800
#define TILE_BYTES  (TILE_FLOATS * 4)   // 51200
#define WARP_FLOATS (32 * ORDER)        // 800
#define WARP_BYTES  (WARP_FLOATS * 4)   // 3200 (16B-multiple)

__device__ __forceinline__ uint32_t smem_u32(const void* p) {
    uint32_t a;
    asm volatile("{ .reg .u64 x; cvta.to.shared.u64 x, %1; cvt.u32.u64 %0, x; }"
                 : "=r"(a) : "l"(p));
    return a;
}

__global__ __launch_bounds__(RPB, 4)
void parcor_to_lpc_bulk(const float* __restrict__ in, float* __restrict__ out)
{
    extern __shared__ __align__(128) float buf[];   // TILE_FLOATS
    __shared__ __align__(8) unsigned long long mbar;

    const int t = threadIdx.x;
    const int w = t >> 5;
    const uint32_t buf_a  = smem_u32(buf);
    const uint32_t mbar_a = smem_u32(&mbar);

    // streaming data: no reuse in L2, evict first
    uint64_t pol;
    asm volatile("createpolicy.fractional.L2::evict_first.b64 %0, 1.0;" : "=l"(pol));

    const float* gsrc = in  + (size_t)blockIdx.x * TILE_FLOATS;
    float*       gdst = out + (size_t)blockIdx.x * TILE_FLOATS;

    // ---- one bulk G->S load for the whole tile ----
    if (t == 0) {
        asm volatile("mbarrier.init.shared.b64 [%0], 1;" :: "r"(mbar_a) : "memory");
        asm volatile("fence.proxy.async.shared::cta;" ::: "memory");
        asm volatile("mbarrier.arrive.expect_tx.shared.b64 _, [%0], %1;"
                     :: "r"(mbar_a), "r"((uint32_t)TILE_BYTES) : "memory");
        asm volatile("cp.async.bulk.shared::cta.global.mbarrier::complete_tx::bytes"
                     ".L2::cache_hint [%0], [%1], %2, [%3], %4;"
                     :: "r"(buf_a), "l"(gsrc), "r"((uint32_t)TILE_BYTES),
                        "r"(mbar_a), "l"(pol)
                     : "memory");
    }
    __syncthreads();   // mbar init visible to all waiters

    // ---- all threads wait for tile arrival ----
    {
        uint32_t done;
        asm volatile(
            "{\n\t.reg .pred p;\n\t"
            "mbarrier.try_wait.parity.acquire.cta.shared::cta.b64 p, [%1], 0;\n\t"
            "selp.b32 %0, 1, 0, p;\n\t}"
            : "=r"(done) : "r"(mbar_a) : "memory");
        if (!done) {
            asm volatile(
                "{\n\t.reg .pred P1;\n\t"
                "WL_%=:\n\t"
                "mbarrier.try_wait.parity.acquire.cta.shared::cta.b64 P1, [%0], 0, 0x989680;\n\t"
                "@P1 bra.uni WD_%=;\n\t"
                "bra.uni WL_%=;\n\t"
                "WD_%=:\n\t}"
                :: "r"(mbar_a) : "memory");
        }
    }

    // ---- row -> registers (stride-25 words: gcd(25,32)=1, conflict-free) ----
    float a[ORDER];
    float* bp = buf + t * ORDER;
    #pragma unroll
    for (int i = 0; i < ORDER; ++i) a[i] = bp[i];

    // ---- Levinson step-up, fully unrolled; a[m]==k[m] when step m runs ----
    #pragma unroll
    for (int m = 2; m < ORDER; ++m) {
        const float km = a[m];
        #pragma unroll
        for (int j = 1; 2 * j < m; ++j) {
            const float tj = a[j];
            const float tk = a[m - j];
            a[j]     = fmaf(km, tk, tj);
            a[m - j] = fmaf(km, tj, tk);
        }
        if ((m & 1) == 0) {
            const int j = m >> 1;
            a[j] = fmaf(km, a[j], a[j]);
        }
    }

    // ---- write back to OWN slots ----
    #pragma unroll
    for (int i = 0; i < ORDER; ++i) bp[i] = a[i];

    // ---- per-warp bulk store: warp's 3200B region written only by its own
    //      lanes -> __syncwarp suffices; no CTA-level store barrier ----
    __syncwarp();
    if ((t & 31) == 0) {
        asm volatile("fence.proxy.async.shared::cta;" ::: "memory");
        asm volatile("cp.async.bulk.global.shared::cta.bulk_group"
                     ".L2::cache_hint [%0], [%1], %2, %3;"
                     :: "l"(gdst + w * WARP_FLOATS),
                        "r"(buf_a + (uint32_t)(w * WARP_BYTES)),
                        "r"((uint32_t)WARP_BYTES), "l"(pol) : "memory");
        asm volatile("cp.async.bulk.commit_group;" ::: "memory");
        // smem must be fully read by the bulk engine before CTA exit
        asm volatile("cp.async.bulk.wait_group.read 0;" ::: "memory");
    }
}

// Fallback for row counts not divisible by RPB (not hit by the bench shape).
__global__ void parcor_to_lpc_scalar(const float* __restrict__ in,
                                     float* __restrict__ out, int rows)
{
    int r = blockIdx.x * blockDim.x + threadIdx.x;
    if (r >= rows) return;
    float a[ORDER];
    #pragma unroll
    for (int i = 0; i < ORDER; ++i) a[i] = in[(size_t)r * ORDER + i];
    #pragma unroll
    for (int m = 2; m < ORDER; ++m) {
        const float km = a[m];
        #pragma unroll
        for (int j = 1; 2 * j < m; ++j) {
            const float tj = a[j];
            const float tk = a[m - j];
            a[j]     = fmaf(km, tk, tj);
            a[m - j] = fmaf(km, tj, tk);
        }
        if ((m & 1) == 0) { const int j = m >> 1; a[j] = fmaf(km, a[j], a[j]); }
    }
    #pragma unroll
    for (int i = 0; i < ORDER; ++i) out[(size_t)r * ORDER + i] = a[i];
}

extern "C" void kernel_launch(void* const* d_in, const int* in_sizes, int n_in,
                              void* d_out, int out_size)
{
    const float* k = (const float*)d_in[0];
    float* out = (float*)d_out;

    const int total_elems = in_sizes[0];
    const int rows = total_elems / ORDER;

    if (rows % RPB == 0) {
        cudaFuncSetAttribute(parcor_to_lpc_bulk,
                             cudaFuncAttributeMaxDynamicSharedMemorySize, TILE_BYTES);
        parcor_to_lpc_bulk<<<rows / RPB, RPB, TILE_BYTES>>>(k, out);
    } else {
        parcor_to_lpc_scalar<<<(rows + 255) / 256, 256>>>(k, out, rows);
    }
}

// round 11
// speedup vs baseline: 1.0179x; 1.0179x over previous
#include <cuda_runtime.h>
#include <cstdint>

// PARCOR -> LPC (Levinson step-up), rows x 25 f32. HBM-bound.
// Fully warp-autonomous: each warp bulk-loads its own 3200 B slice (own
// mbarrier), computes, bulk-stores its own slice. No CTA-level barriers.
// 256 thr, 25.6 KB smem, 8 CTAs/SM.

#define ORDER 25
#define RPB   256                       // rows per tile, one thread per row
#define NWARP (RPB / 32)                // 8
#define TILE_FLOATS (RPB * ORDER)       // 6400
#define TILE_BYTES  (TILE_FLOATS * 4)   // 25600
#define WARP_FLOATS (32 * ORDER)        // 800
#define WARP_BYTES  (WARP_FLOATS * 4)   // 3200 (16B-multiple)

__device__ __forceinline__ uint32_t smem_u32(const void* p) {
    uint32_t a;
    asm volatile("{ .reg .u64 x; cvta.to.shared.u64 x, %1; cvt.u32.u64 %0, x; }"
                 : "=r"(a) : "l"(p));
    return a;
}

__global__ __launch_bounds__(RPB, 8)
void parcor_to_lpc_warp(const float* __restrict__ in, float* __restrict__ out)
{
    extern __shared__ __align__(128) float buf[];        // TILE_FLOATS
    __shared__ __align__(8) unsigned long long mbar[NWARP];

    const int t    = threadIdx.x;
    const int w    = t >> 5;
    const int lane = t & 31;

    const uint32_t wbuf_a = smem_u32(buf) + (uint32_t)(w * WARP_BYTES);
    const uint32_t mbar_a = smem_u32(&mbar[w]);

    const float* gsrc = in  + (size_t)blockIdx.x * TILE_FLOATS + (size_t)w * WARP_FLOATS;
    float*       gdst = out + (size_t)blockIdx.x * TILE_FLOATS + (size_t)w * WARP_FLOATS;

    // ---- per-warp bulk load of this warp's 3200 B slice ----
    if (lane == 0) {
        asm volatile("mbarrier.init.shared.b64 [%0], 1;" :: "r"(mbar_a) : "memory");
        asm volatile("fence.proxy.async.shared::cta;" ::: "memory");
        asm volatile("mbarrier.arrive.expect_tx.shared.b64 _, [%0], %1;"
                     :: "r"(mbar_a), "r"((uint32_t)WARP_BYTES) : "memory");
        asm volatile("cp.async.bulk.shared::cta.global.mbarrier::complete_tx::bytes "
                     "[%0], [%1], %2, [%3];"
                     :: "r"(wbuf_a), "l"(gsrc), "r"((uint32_t)WARP_BYTES), "r"(mbar_a)
                     : "memory");
    }
    __syncwarp();   // init + TMA issued; only this warp touches this mbarrier

    // ---- warp waits only on its own slice ----
    {
        uint32_t done;
        asm volatile(
            "{\n\t.reg .pred p;\n\t"
            "mbarrier.try_wait.parity.acquire.cta.shared::cta.b64 p, [%1], 0;\n\t"
            "selp.b32 %0, 1, 0, p;\n\t}"
            : "=r"(done) : "r"(mbar_a) : "memory");
        if (!done) {
            asm volatile(
                "{\n\t.reg .pred P1;\n\t"
                "WL_%=:\n\t"
                "mbarrier.try_wait.parity.acquire.cta.shared::cta.b64 P1, [%0], 0, 0x989680;\n\t"
                "@P1 bra.uni WD_%=;\n\t"
                "bra.uni WL_%=;\n\t"
                "WD_%=:\n\t}"
                :: "r"(mbar_a) : "memory");
        }
    }

    // ---- row -> registers (stride-25 words: gcd(25,32)=1, conflict-free) ----
    float a[ORDER];
    float* bp = buf + (size_t)w * WARP_FLOATS + lane * ORDER;
    #pragma unroll
    for (int i = 0; i < ORDER; ++i) a[i] = bp[i];

    // ---- Levinson step-up, fully unrolled; a[m]==k[m] when step m runs ----
    #pragma unroll
    for (int m = 2; m < ORDER; ++m) {
        const float km = a[m];
        #pragma unroll
        for (int j = 1; 2 * j < m; ++j) {
            const float tj = a[j];
            const float tk = a[m - j];
            a[j]     = fmaf(km, tk, tj);
            a[m - j] = fmaf(km, tj, tk);
        }
        if ((m & 1) == 0) {
            const int j = m >> 1;
            a[j] = fmaf(km, a[j], a[j]);
        }
    }

    // ---- write back to OWN slots, per-warp bulk store ----
    #pragma unroll
    for (int i = 0; i < ORDER; ++i) bp[i] = a[i];

    __syncwarp();
    if (lane == 0) {
        asm volatile("fence.proxy.async.shared::cta;" ::: "memory");
        asm volatile("cp.async.bulk.global.shared::cta.bulk_group [%0], [%1], %2;"
                     :: "l"(gdst), "r"(wbuf_a), "r"((uint32_t)WARP_BYTES) : "memory");
        asm volatile("cp.async.bulk.commit_group;" ::: "memory");
        // smem must be fully read by the bulk engine before CTA exit
        asm volatile("cp.async.bulk.wait_group.read 0;" ::: "memory");
    }
}

// Fallback for row counts not divisible by RPB (not hit by the bench shape).
__global__ void parcor_to_lpc_scalar(const float* __restrict__ in,
                                     float* __restrict__ out, int rows)
{
    int r = blockIdx.x * blockDim.x + threadIdx.x;
    if (r >= rows) return;
    float a[ORDER];
    #pragma unroll
    for (int i = 0; i < ORDER; ++i) a[i] = in[(size_t)r * ORDER + i];
    #pragma unroll
    for (int m = 2; m < ORDER; ++m) {
        const float km = a[m];
        #pragma unroll
        for (int j = 1; 2 * j < m; ++j) {
            const float tj = a[j];
            const float tk = a[m - j];
            a[j]     = fmaf(km, tk, tj);
            a[m - j] = fmaf(km, tj, tk);
        }
        if ((m & 1) == 0) { const int j = m >> 1; a[j] = fmaf(km, a[j], a[j]); }
    }
    #pragma unroll
    for (int i = 0; i < ORDER; ++i) out[(size_t)r * ORDER + i] = a[i];
}

extern "C" void kernel_launch(void* const* d_in, const int* in_sizes, int n_in,
                              void* d_out, int out_size)
{
    const float* k = (const float*)d_in[0];
    float* out = (float*)d_out;

    const int total_elems = in_sizes[0];
    const int rows = total_elems / ORDER;

    if (rows % RPB == 0) {
        cudaFuncSetAttribute(parcor_to_lpc_warp,
                             cudaFuncAttributeMaxDynamicSharedMemorySize, TILE_BYTES);
        parcor_to_lpc_warp<<<rows / RPB, RPB, TILE_BYTES>>>(k, out);
    } else {
        parcor_to_lpc_scalar<<<(rows + 255) / 256, 256>>>(k, out, rows);
    }
}